// round 2
// baseline (speedup 1.0000x reference)
#include <cuda_runtime.h>
#include <cuda_bf16.h>

// Problem constants
#define NB 4          // batch
#define LL 2048       // seq len
#define EQ 512        // E_Q == E_TOTAL
#define HH 8          // heads
#define HD 64         // head dim
#define NF 8          // forecast steps
#define BHCNT (NB*HH) // 32

// ------------------- device scratch (no allocation allowed) -------------------
__device__ float g_q[BHCNT * LL * HD];       // [bh, s, d]   16 MB
__device__ float g_k[BHCNT * LL * HD];       // [bh, s, d]   16 MB
__device__ float g_v[BHCNT * LL * HD];       // [bh, s, d]   16 MB
__device__ float g_attn[NB * LL * EQ];       // [b, s, h*64+d] 16 MB
__device__ float g_M[NF * HH * HD * HD];     // T^{n+1} per (n,h)
__device__ float g_wbig[NF * EQ * EQ];       // fused (T^{n+1} Wo_h) stacked per n, 8 MB

// =============================================================================
// Kernel P1: per-head T = I + (Xi - Xi^T); powers T^{n+1} -> g_M[n][h]
// grid: 8 blocks (one per head), 256 threads
// =============================================================================
__global__ void prep_powers(const float* __restrict__ Xi) {
    int h = blockIdx.x;
    __shared__ float T[HD][HD];
    __shared__ float Ma[HD][HD];
    __shared__ float Mb[HD][HD];
    int t = threadIdx.x;

    for (int idx = t; idx < HD * HD; idx += 256) {
        int r = idx >> 6, c = idx & 63;
        float a = Xi[h * HD * HD + r * HD + c] - Xi[h * HD * HD + c * HD + r];
        float tv = a + ((r == c) ? 1.0f : 0.0f);
        T[r][c] = tv;
        Ma[r][c] = tv;   // M_1 = T
    }
    __syncthreads();

    for (int n = 0; n < NF; n++) {
        // store Ma = T^{n+1}
        for (int idx = t; idx < HD * HD; idx += 256)
            g_M[(n * HH + h) * HD * HD + idx] = Ma[idx >> 6][idx & 63];
        if (n < NF - 1) {
            // Mb = Ma @ T
            for (int idx = t; idx < HD * HD; idx += 256) {
                int r = idx >> 6, c = idx & 63;
                float sum = 0.0f;
                #pragma unroll 16
                for (int j = 0; j < HD; j++) sum += Ma[r][j] * T[j][c];
                Mb[r][c] = sum;
            }
            __syncthreads();
            for (int idx = t; idx < HD * HD; idx += 256)
                Ma[idx >> 6][idx & 63] = Mb[idx >> 6][idx & 63];
            __syncthreads();
        }
    }
}

// =============================================================================
// Kernel P2: g_wbig[n][h*64+r][e] = sum_c T^{n+1}[r][c] * Wo[h*64+c][e]
// grid: 64 blocks (n*8+h), 256 threads
// =============================================================================
__global__ void prep_wbig(const float* __restrict__ Wo) {
    int nh = blockIdx.x;
    int n = nh >> 3, h = nh & 7;
    __shared__ float M[HD][HD];
    int t = threadIdx.x;
    for (int idx = t; idx < HD * HD; idx += 256)
        M[idx >> 6][idx & 63] = g_M[nh * HD * HD + idx];
    __syncthreads();

    for (int idx = t; idx < HD * EQ; idx += 256) {
        int r = idx >> 9, e = idx & 511;
        float sum = 0.0f;
        #pragma unroll 16
        for (int c = 0; c < HD; c++)
            sum += M[r][c] * Wo[(h * HD + c) * EQ + e];
        g_wbig[(n * EQ + h * HD + r) * EQ + e] = sum;
    }
}

// =============================================================================
// Kernel G1: QKV projection.
//   C[m, jg] = query[m, :] @ Wqkv[:, jg] + bqkv[jg]
//   scatter into g_q/g_k/g_v in [bh, s, d] layout.
// 128x128x16 tile, 256 threads, 8x8 per thread.
// grid: (64, 12)
// =============================================================================
__global__ __launch_bounds__(256) void qkv_gemm(const float* __restrict__ A,
                                                const float* __restrict__ B,
                                                const float* __restrict__ bias) {
    const int K = EQ, NN = 3 * EQ;
    __shared__ __align__(16) float As[16][128];
    __shared__ __align__(16) float Bs[16][128];
    int m0 = blockIdx.x * 128;
    int n0 = blockIdx.y * 128;
    int tid = threadIdx.x;
    int tx = tid & 15, ty = tid >> 4;

    float acc[8][8] = {};

    // A loads: 128 rows x 16 cols = 2048 floats = 512 float4; 256 threads -> 2 each
    int arow = tid >> 1;              // 0..127
    int acol4 = (tid & 1) * 8;        // 0 or 8 (two float4 per row half)
    // B loads: 16 rows x 128 cols = 2048 floats = 512 float4; 2 per thread
    int brow = tid >> 5;              // 0..7
    int bcol4 = (tid & 31) * 4;

    for (int k0 = 0; k0 < K; k0 += 16) {
        #pragma unroll
        for (int u = 0; u < 2; u++) {
            float4 av = *(const float4*)&A[(m0 + arow) * K + k0 + acol4 + u * 4];
            As[acol4 + u * 4 + 0][arow] = av.x;
            As[acol4 + u * 4 + 1][arow] = av.y;
            As[acol4 + u * 4 + 2][arow] = av.z;
            As[acol4 + u * 4 + 3][arow] = av.w;
        }
        #pragma unroll
        for (int u = 0; u < 2; u++) {
            float4 bv = *(const float4*)&B[(k0 + brow + u * 8) * NN + n0 + bcol4];
            *(float4*)&Bs[brow + u * 8][bcol4] = bv;
        }
        __syncthreads();
        #pragma unroll
        for (int k = 0; k < 16; k++) {
            float4 a0 = *(const float4*)&As[k][ty * 8];
            float4 a1 = *(const float4*)&As[k][ty * 8 + 4];
            float4 b0 = *(const float4*)&Bs[k][tx * 8];
            float4 b1 = *(const float4*)&Bs[k][tx * 8 + 4];
            float ar[8] = {a0.x, a0.y, a0.z, a0.w, a1.x, a1.y, a1.z, a1.w};
            float br[8] = {b0.x, b0.y, b0.z, b0.w, b1.x, b1.y, b1.z, b1.w};
            #pragma unroll
            for (int i = 0; i < 8; i++)
                #pragma unroll
                for (int j = 0; j < 8; j++)
                    acc[i][j] += ar[i] * br[j];
        }
        __syncthreads();
    }

    // epilogue: scatter to q/k/v [bh, s, d]
    #pragma unroll
    for (int i = 0; i < 8; i++) {
        int m = m0 + ty * 8 + i;
        int b = m >> 11, s = m & 2047;
        #pragma unroll
        for (int j = 0; j < 8; j += 4) {
            int jg = n0 + tx * 8 + j;
            int which = jg >> 9;
            int rem = jg & 511;
            int h = rem >> 6, d = rem & 63;
            float* dst = (which == 0) ? g_q : ((which == 1) ? g_k : g_v);
            float4 v;
            v.x = acc[i][j + 0] + bias[jg + 0];
            v.y = acc[i][j + 1] + bias[jg + 1];
            v.z = acc[i][j + 2] + bias[jg + 2];
            v.w = acc[i][j + 3] + bias[jg + 3];
            *(float4*)&dst[(((b << 3) + h) * LL + s) * HD + d] = v;
        }
    }
}

// =============================================================================
// Kernel A: causal flash attention, fp32.
//   One thread per query row; 128 rows per block; K/V staged in smem (64-row
//   tiles) and read via broadcast. Output written directly into the
//   [b, s, h*64+d] concatenated layout for the fused output GEMM.
// grid: (16, 32)  block: 128
// =============================================================================
__global__ __launch_bounds__(128) void attn_kernel() {
    const int BMq = 128, BNk = 64;
    int bh = blockIdx.y;
    // reverse order so heaviest (largest causal extent) tiles launch first
    int qt = (gridDim.x - 1 - blockIdx.x);
    int q0 = qt * BMq;
    int t = threadIdx.x;
    int row = q0 + t;
    const float scale = 0.125f;  // 1/sqrt(64)

    __shared__ __align__(16) float4 kt[BNk][16];
    __shared__ __align__(16) float4 vt[BNk][16];

    const float4* qptr = (const float4*)(g_q + (bh * LL + row) * HD);
    float4 qv[16];
    #pragma unroll
    for (int i = 0; i < 16; i++) qv[i] = qptr[i];

    float4 o[16];
    #pragma unroll
    for (int i = 0; i < 16; i++) o[i] = make_float4(0.f, 0.f, 0.f, 0.f);
    float mmax = -1e30f, lsum = 0.0f;

    int jend = q0 + BMq;  // exclusive key bound needed by this block
    for (int j0 = 0; j0 < jend; j0 += BNk) {
        const float4* kg = (const float4*)(g_k + (bh * LL + j0) * HD);
        const float4* vg = (const float4*)(g_v + (bh * LL + j0) * HD);
        #pragma unroll
        for (int i = 0; i < 8; i++) {
            int idx = t + i * 128;
            ((float4*)kt)[idx] = kg[idx];
            ((float4*)vt)[idx] = vg[idx];
        }
        __syncthreads();

        int jmax = row - j0 + 1;
        if (jmax > BNk) jmax = BNk;
        for (int j = 0; j < jmax; j++) {
            float s0 = 0.f, s1 = 0.f, s2 = 0.f, s3 = 0.f;
            #pragma unroll
            for (int i = 0; i < 16; i += 4) {
                float4 k0 = kt[j][i + 0];
                float4 k1 = kt[j][i + 1];
                float4 k2 = kt[j][i + 2];
                float4 k3 = kt[j][i + 3];
                s0 += qv[i + 0].x * k0.x + qv[i + 0].y * k0.y + qv[i + 0].z * k0.z + qv[i + 0].w * k0.w;
                s1 += qv[i + 1].x * k1.x + qv[i + 1].y * k1.y + qv[i + 1].z * k1.z + qv[i + 1].w * k1.w;
                s2 += qv[i + 2].x * k2.x + qv[i + 2].y * k2.y + qv[i + 2].z * k2.z + qv[i + 2].w * k2.w;
                s3 += qv[i + 3].x * k3.x + qv[i + 3].y * k3.y + qv[i + 3].z * k3.z + qv[i + 3].w * k3.w;
            }
            float sc = ((s0 + s1) + (s2 + s3)) * scale;

            if (sc > mmax) {
                float corr = __expf(mmax - sc);
                mmax = sc;
                lsum = lsum * corr + 1.0f;
                #pragma unroll
                for (int i = 0; i < 16; i++) {
                    float4 vv = vt[j][i];
                    o[i].x = o[i].x * corr + vv.x;
                    o[i].y = o[i].y * corr + vv.y;
                    o[i].z = o[i].z * corr + vv.z;
                    o[i].w = o[i].w * corr + vv.w;
                }
            } else {
                float p = __expf(sc - mmax);
                lsum += p;
                #pragma unroll
                for (int i = 0; i < 16; i++) {
                    float4 vv = vt[j][i];
                    o[i].x += p * vv.x;
                    o[i].y += p * vv.y;
                    o[i].z += p * vv.z;
                    o[i].w += p * vv.w;
                }
            }
        }
        __syncthreads();
    }

    float inv = 1.0f / lsum;
    int b = bh >> 3, h = bh & 7;
    float4* op = (float4*)(g_attn + (b * LL + row) * EQ + h * HD);
    #pragma unroll
    for (int i = 0; i < 16; i++) {
        float4 v = o[i];
        v.x *= inv; v.y *= inv; v.z *= inv; v.w *= inv;
        op[i] = v;
    }
}

// =============================================================================
// Kernel G2: fused rollout + output projection.
//   out[b, n, s, e] = g_attn[b, s, :] @ g_wbig[n] + bo[e]
// grid: (64, 4, 8)  — z = forecast step n
// =============================================================================
__global__ __launch_bounds__(256) void out_gemm(const float* __restrict__ bo,
                                                float* __restrict__ out) {
    const int K = EQ, NN = EQ;
    int nz = blockIdx.z;
    const float* Bmat = g_wbig + nz * EQ * EQ;
    __shared__ __align__(16) float As[16][128];
    __shared__ __align__(16) float Bs[16][128];
    int m0 = blockIdx.x * 128;
    int n0 = blockIdx.y * 128;
    int tid = threadIdx.x;
    int tx = tid & 15, ty = tid >> 4;

    float acc[8][8] = {};

    int arow = tid >> 1;
    int acol4 = (tid & 1) * 8;
    int brow = tid >> 5;
    int bcol4 = (tid & 31) * 4;

    for (int k0 = 0; k0 < K; k0 += 16) {
        #pragma unroll
        for (int u = 0; u < 2; u++) {
            float4 av = *(const float4*)&g_attn[(m0 + arow) * K + k0 + acol4 + u * 4];
            As[acol4 + u * 4 + 0][arow] = av.x;
            As[acol4 + u * 4 + 1][arow] = av.y;
            As[acol4 + u * 4 + 2][arow] = av.z;
            As[acol4 + u * 4 + 3][arow] = av.w;
        }
        #pragma unroll
        for (int u = 0; u < 2; u++) {
            float4 bv = *(const float4*)&Bmat[(k0 + brow + u * 8) * NN + n0 + bcol4];
            *(float4*)&Bs[brow + u * 8][bcol4] = bv;
        }
        __syncthreads();
        #pragma unroll
        for (int k = 0; k < 16; k++) {
            float4 a0 = *(const float4*)&As[k][ty * 8];
            float4 a1 = *(const float4*)&As[k][ty * 8 + 4];
            float4 b0 = *(const float4*)&Bs[k][tx * 8];
            float4 b1 = *(const float4*)&Bs[k][tx * 8 + 4];
            float ar[8] = {a0.x, a0.y, a0.z, a0.w, a1.x, a1.y, a1.z, a1.w};
            float br[8] = {b0.x, b0.y, b0.z, b0.w, b1.x, b1.y, b1.z, b1.w};
            #pragma unroll
            for (int i = 0; i < 8; i++)
                #pragma unroll
                for (int j = 0; j < 8; j++)
                    acc[i][j] += ar[i] * br[j];
        }
        __syncthreads();
    }

    #pragma unroll
    for (int i = 0; i < 8; i++) {
        int m = m0 + ty * 8 + i;
        int b = m >> 11, s = m & 2047;
        float* orow = out + (((b * NF + nz) * LL + s) * EQ);
        #pragma unroll
        for (int j = 0; j < 8; j += 4) {
            int e = n0 + tx * 8 + j;
            float4 v;
            v.x = acc[i][j + 0] + bo[e + 0];
            v.y = acc[i][j + 1] + bo[e + 1];
            v.z = acc[i][j + 2] + bo[e + 2];
            v.w = acc[i][j + 3] + bo[e + 3];
            *(float4*)&orow[e] = v;
        }
    }
}

// =============================================================================
extern "C" void kernel_launch(void* const* d_in, const int* in_sizes, int n_in,
                              void* d_out, int out_size) {
    const float* query = (const float*)d_in[0];
    // d_in[1] = key, d_in[2] = value -- unused by reference forward
    const float* Wqkv  = (const float*)d_in[3];
    const float* bqkv  = (const float*)d_in[4];
    const float* Wo    = (const float*)d_in[5];
    const float* bo    = (const float*)d_in[6];
    const float* Xi    = (const float*)d_in[7];
    float* out = (float*)d_out;

    prep_powers<<<HH, 256>>>(Xi);
    prep_wbig<<<NF * HH, 256>>>(Wo);
    qkv_gemm<<<dim3((NB * LL) / 128, (3 * EQ) / 128), 256>>>(query, Wqkv, bqkv);
    attn_kernel<<<dim3(LL / 128, BHCNT), 128>>>();
    out_gemm<<<dim3((NB * LL) / 128, EQ / 128, NF), 256>>>(bo, out);
}

// round 3
// speedup vs baseline: 2.3484x; 2.3484x over previous
#include <cuda_runtime.h>
#include <cuda_bf16.h>
#include <cstdint>

// Problem constants
#define NB 4          // batch
#define LL 2048       // seq len
#define EQ 512        // E_Q == E_TOTAL
#define HH 8          // heads
#define HD 64         // head dim
#define NF 8          // forecast steps
#define BHCNT (NB*HH) // 32

// ------------------- device scratch (no allocation allowed) -------------------
__device__ float g_q[BHCNT * LL * HD];       // [bh, s, d]
__device__ float g_k[BHCNT * LL * HD];
__device__ float g_v[BHCNT * LL * HD];
__device__ float g_attn[NB * LL * EQ];       // [b, s, h*64+d]
__device__ float g_M[NF * HH * HD * HD];     // T^{n+1} per (n,h)
__device__ float g_wbig[NF * EQ * EQ];       // fused (T^{n+1} Wo_h)

// ------------------- tf32 helpers -------------------
__device__ __forceinline__ uint32_t f2tf(float x) {
    uint32_t r;
    asm("cvt.rna.tf32.f32 %0, %1;" : "=r"(r) : "f"(x));
    return r;
}

// D(+=C) = A(16x8 tf32 row) * B(8x8 tf32 col) ; fp32 accum
__device__ __forceinline__ void mma_tf32(float d[4], const uint32_t a[4], const uint32_t b[2]) {
    asm volatile(
        "mma.sync.aligned.m16n8k8.row.col.f32.tf32.tf32.f32 "
        "{%0,%1,%2,%3}, {%4,%5,%6,%7}, {%8,%9}, {%0,%1,%2,%3};\n"
        : "+f"(d[0]), "+f"(d[1]), "+f"(d[2]), "+f"(d[3])
        : "r"(a[0]), "r"(a[1]), "r"(a[2]), "r"(a[3]), "r"(b[0]), "r"(b[1]));
}

// =============================================================================
// P1: per-head T = I + (Xi - Xi^T); powers T^{n+1} -> g_M[n][h]
// =============================================================================
__global__ void prep_powers(const float* __restrict__ Xi) {
    int h = blockIdx.x;
    __shared__ float T[HD][HD];
    __shared__ float Ma[HD][HD];
    __shared__ float Mb[HD][HD];
    int t = threadIdx.x;

    for (int idx = t; idx < HD * HD; idx += 256) {
        int r = idx >> 6, c = idx & 63;
        float a = Xi[h * HD * HD + r * HD + c] - Xi[h * HD * HD + c * HD + r];
        float tv = a + ((r == c) ? 1.0f : 0.0f);
        T[r][c] = tv;
        Ma[r][c] = tv;
    }
    __syncthreads();

    for (int n = 0; n < NF; n++) {
        for (int idx = t; idx < HD * HD; idx += 256)
            g_M[(n * HH + h) * HD * HD + idx] = Ma[idx >> 6][idx & 63];
        if (n < NF - 1) {
            for (int idx = t; idx < HD * HD; idx += 256) {
                int r = idx >> 6, c = idx & 63;
                float sum = 0.0f;
                #pragma unroll 16
                for (int j = 0; j < HD; j++) sum += Ma[r][j] * T[j][c];
                Mb[r][c] = sum;
            }
            __syncthreads();
            for (int idx = t; idx < HD * HD; idx += 256)
                Ma[idx >> 6][idx & 63] = Mb[idx >> 6][idx & 63];
            __syncthreads();
        }
    }
}

// =============================================================================
// P2: g_wbig[n][h*64+r][e] = sum_c T^{n+1}[r][c] * Wo[h*64+c][e]
// =============================================================================
__global__ void prep_wbig(const float* __restrict__ Wo) {
    int nh = blockIdx.x;
    int n = nh >> 3, h = nh & 7;
    __shared__ float M[HD][HD];
    int t = threadIdx.x;
    for (int idx = t; idx < HD * HD; idx += 256)
        M[idx >> 6][idx & 63] = g_M[nh * HD * HD + idx];
    __syncthreads();

    for (int idx = t; idx < HD * EQ; idx += 256) {
        int r = idx >> 9, e = idx & 511;
        float sum = 0.0f;
        #pragma unroll 16
        for (int c = 0; c < HD; c++)
            sum += M[r][c] * Wo[(h * HD + c) * EQ + e];
        g_wbig[(n * EQ + h * HD + r) * EQ + e] = sum;
    }
}

// =============================================================================
// Shared 128x128x512 tf32 MMA tile core. 256 threads = 8 warps (2m x 4n),
// warp tile 64x32, mma m16n8k8. A pre-offset by m0*lda, B pre-offset by n0.
// =============================================================================
__device__ __forceinline__ void gemm128_tf32(
    const float* __restrict__ A, int lda,
    const float* __restrict__ B, int ldb,
    float acc[4][4][4])
{
    __shared__ uint32_t As[128][36];   // [m][k], pad -> bank = 4m+k
    __shared__ uint32_t Bs[32][136];   // [k][n], pad -> bank = 8k+n

    int tid = threadIdx.x;
    int wid = tid >> 5, lane = tid & 31;
    int wm = (wid & 1) * 64, wn = (wid >> 1) * 32;
    int lq = lane >> 2, lr = lane & 3;

    int ar = tid >> 1, ac = (tid & 1) * 16;
    int br = tid >> 3, bc = (tid & 7) * 16;

    for (int k0 = 0; k0 < 512; k0 += 32) {
        #pragma unroll
        for (int u = 0; u < 4; u++) {
            float4 v = *(const float4*)&A[ar * lda + k0 + ac + 4 * u];
            *(uint4*)&As[ar][ac + 4 * u] =
                make_uint4(f2tf(v.x), f2tf(v.y), f2tf(v.z), f2tf(v.w));
        }
        #pragma unroll
        for (int u = 0; u < 4; u++) {
            float4 v = *(const float4*)&B[(k0 + br) * ldb + bc + 4 * u];
            *(uint4*)&Bs[br][bc + 4 * u] =
                make_uint4(f2tf(v.x), f2tf(v.y), f2tf(v.z), f2tf(v.w));
        }
        __syncthreads();

        #pragma unroll
        for (int kk = 0; kk < 32; kk += 8) {
            uint32_t af[4][4], bf[4][2];
            #pragma unroll
            for (int i = 0; i < 4; i++) {
                int r = wm + 16 * i + lq;
                int c = kk + lr;
                af[i][0] = As[r][c];     af[i][1] = As[r + 8][c];
                af[i][2] = As[r][c + 4]; af[i][3] = As[r + 8][c + 4];
            }
            #pragma unroll
            for (int j = 0; j < 4; j++) {
                int n = wn + 8 * j + lq;
                int c = kk + lr;
                bf[j][0] = Bs[c][n]; bf[j][1] = Bs[c + 4][n];
            }
            #pragma unroll
            for (int i = 0; i < 4; i++)
                #pragma unroll
                for (int j = 0; j < 4; j++)
                    mma_tf32(acc[i][j], af[i], bf[j]);
        }
        __syncthreads();
    }
}

// =============================================================================
// G1: QKV projection -> scatter to g_q/g_k/g_v [bh, s, d]
// grid (64, 12), 256 threads
// =============================================================================
__global__ __launch_bounds__(256) void qkv_gemm(const float* __restrict__ A,
                                                const float* __restrict__ B,
                                                const float* __restrict__ bias) {
    float acc[4][4][4] = {};
    int m0 = blockIdx.x * 128, n0 = blockIdx.y * 128;
    gemm128_tf32(A + (long)m0 * 512, 512, B + n0, 1536, acc);

    int tid = threadIdx.x;
    int wid = tid >> 5, lane = tid & 31;
    int wm = (wid & 1) * 64, wn = (wid >> 1) * 32;
    int lq = lane >> 2, lr = lane & 3;

    #pragma unroll
    for (int i = 0; i < 4; i++) {
        int mrow = m0 + wm + 16 * i + lq;
        int b = mrow >> 11, s = mrow & 2047;
        #pragma unroll
        for (int j = 0; j < 4; j++) {
            int col = n0 + wn + 8 * j + 2 * lr;
            int which = col >> 9, rem = col & 511;
            int h = rem >> 6, d = rem & 63;
            float* dst = (which == 0) ? g_q : ((which == 1) ? g_k : g_v);
            float b0 = bias[col], b1 = bias[col + 1];
            float2 v0 = {acc[i][j][0] + b0, acc[i][j][1] + b1};
            float2 v1 = {acc[i][j][2] + b0, acc[i][j][3] + b1};
            long base = (((long)(b << 3) + h) * LL + s) * HD + d;
            *(float2*)&dst[base] = v0;
            *(float2*)&dst[base + 8 * HD] = v1;
        }
    }
}

// =============================================================================
// A: causal flash attention with tf32 MMA.
//   BM=64 q rows, BN=32 keys, 4 warps (each 16 q-rows). Scale folded into Q.
// grid (32, 32), 128 threads
// =============================================================================
__global__ __launch_bounds__(128) void attn_kernel() {
    __shared__ uint32_t Qs[64][68];      // [row][d]   bank = 4r+c
    __shared__ uint32_t Ks[32][68];      // [key][d]
    __shared__ uint32_t Vs[32][72];      // [key][d]   bank = 8k+n
    __shared__ uint32_t Ps[4][16][36];   // per-warp P [row][key]

    int bh = blockIdx.y;
    int qt = gridDim.x - 1 - blockIdx.x;   // heavy tiles first
    int q0 = qt * 64;
    int t = threadIdx.x;
    int w = t >> 5, lane = t & 31;
    int lq = lane >> 2, lr = lane & 3;
    const float scale = 0.125f;

    // stage Q (pre-scaled)
    const float* qg = g_q + ((long)bh * LL + q0) * HD;
    #pragma unroll
    for (int i = 0; i < 8; i++) {
        int idx = t + i * 128;
        int r = idx >> 4, c = (idx & 15) * 4;
        float4 v = *(const float4*)&qg[r * HD + c];
        *(uint4*)&Qs[r][c] = make_uint4(f2tf(v.x * scale), f2tf(v.y * scale),
                                        f2tf(v.z * scale), f2tf(v.w * scale));
    }
    __syncthreads();

    // preload Q fragments (warp rows w*16 .. w*16+15)
    uint32_t qa[8][4];
    #pragma unroll
    for (int s = 0; s < 8; s++) {
        int r = w * 16 + lq, c = s * 8 + lr;
        qa[s][0] = Qs[r][c];     qa[s][1] = Qs[r + 8][c];
        qa[s][2] = Qs[r][c + 4]; qa[s][3] = Qs[r + 8][c + 4];
    }

    float oacc[8][4];
    #pragma unroll
    for (int n_ = 0; n_ < 8; n_++)
        #pragma unroll
        for (int x = 0; x < 4; x++) oacc[n_][x] = 0.0f;
    float m0v = -1e30f, m1v = -1e30f, l0 = 0.0f, l1 = 0.0f;

    int r0g = q0 + w * 16 + lq;          // global row of this thread's row-0
    int wmaxrow = q0 + w * 16 + 15;
    int ntiles = 2 * qt + 2;

    for (int jt = 0; jt < ntiles; jt++) {
        int j0 = jt * 32;
        __syncthreads();
        const float* kg = g_k + ((long)bh * LL + j0) * HD;
        const float* vg = g_v + ((long)bh * LL + j0) * HD;
        #pragma unroll
        for (int i = 0; i < 4; i++) {
            int idx = t + i * 128;
            int r = idx >> 4, c = (idx & 15) * 4;
            float4 kv = *(const float4*)&kg[r * HD + c];
            *(uint4*)&Ks[r][c] = make_uint4(f2tf(kv.x), f2tf(kv.y), f2tf(kv.z), f2tf(kv.w));
            float4 vv = *(const float4*)&vg[r * HD + c];
            *(uint4*)&Vs[r][c] = make_uint4(f2tf(vv.x), f2tf(vv.y), f2tf(vv.z), f2tf(vv.w));
        }
        __syncthreads();

        if (j0 > wmaxrow) continue;       // fully-masked for this warp

        // ---- S = Q K^T (pre-scaled) ----
        float sacc[4][4] = {};
        #pragma unroll
        for (int s = 0; s < 8; s++) {
            uint32_t bf[4][2];
            #pragma unroll
            for (int j = 0; j < 4; j++) {
                int n = j * 8 + lq, c = s * 8 + lr;
                bf[j][0] = Ks[n][c]; bf[j][1] = Ks[n][c + 4];
            }
            #pragma unroll
            for (int j = 0; j < 4; j++) mma_tf32(sacc[j], qa[s], bf[j]);
        }

        // ---- causal mask (only near diagonal) ----
        if (j0 + 31 > q0) {
            #pragma unroll
            for (int j = 0; j < 4; j++) {
                int kc = j0 + j * 8 + 2 * lr;
                if (kc     > r0g)     sacc[j][0] = -1e30f;
                if (kc + 1 > r0g)     sacc[j][1] = -1e30f;
                if (kc     > r0g + 8) sacc[j][2] = -1e30f;
                if (kc + 1 > r0g + 8) sacc[j][3] = -1e30f;
            }
        }

        // ---- online softmax ----
        float rm0 = -1e30f, rm1 = -1e30f;
        #pragma unroll
        for (int j = 0; j < 4; j++) {
            rm0 = fmaxf(rm0, fmaxf(sacc[j][0], sacc[j][1]));
            rm1 = fmaxf(rm1, fmaxf(sacc[j][2], sacc[j][3]));
        }
        rm0 = fmaxf(rm0, __shfl_xor_sync(0xffffffffu, rm0, 1));
        rm0 = fmaxf(rm0, __shfl_xor_sync(0xffffffffu, rm0, 2));
        rm1 = fmaxf(rm1, __shfl_xor_sync(0xffffffffu, rm1, 1));
        rm1 = fmaxf(rm1, __shfl_xor_sync(0xffffffffu, rm1, 2));
        float nm0 = fmaxf(m0v, rm0), nm1 = fmaxf(m1v, rm1);
        float c0 = __expf(m0v - nm0), c1 = __expf(m1v - nm1);
        m0v = nm0; m1v = nm1;

        float rs0 = 0.0f, rs1 = 0.0f;
        uint32_t pu[4][4];
        #pragma unroll
        for (int j = 0; j < 4; j++) {
            float p0 = __expf(sacc[j][0] - nm0);
            float p1 = __expf(sacc[j][1] - nm0);
            float p2 = __expf(sacc[j][2] - nm1);
            float p3 = __expf(sacc[j][3] - nm1);
            rs0 += p0 + p1; rs1 += p2 + p3;
            pu[j][0] = f2tf(p0); pu[j][1] = f2tf(p1);
            pu[j][2] = f2tf(p2); pu[j][3] = f2tf(p3);
        }
        rs0 += __shfl_xor_sync(0xffffffffu, rs0, 1);
        rs0 += __shfl_xor_sync(0xffffffffu, rs0, 2);
        rs1 += __shfl_xor_sync(0xffffffffu, rs1, 1);
        rs1 += __shfl_xor_sync(0xffffffffu, rs1, 2);
        l0 = l0 * c0 + rs0;
        l1 = l1 * c1 + rs1;
        #pragma unroll
        for (int n_ = 0; n_ < 8; n_++) {
            oacc[n_][0] *= c0; oacc[n_][1] *= c0;
            oacc[n_][2] *= c1; oacc[n_][3] *= c1;
        }

        // ---- P -> smem (per warp), reload as A-frags ----
        __syncwarp();
        #pragma unroll
        for (int j = 0; j < 4; j++) {
            *(uint2*)&Ps[w][lq][j * 8 + 2 * lr]     = make_uint2(pu[j][0], pu[j][1]);
            *(uint2*)&Ps[w][lq + 8][j * 8 + 2 * lr] = make_uint2(pu[j][2], pu[j][3]);
        }
        __syncwarp();

        // ---- O += P V ----
        #pragma unroll
        for (int s = 0; s < 4; s++) {
            uint32_t pa[4];
            int c = s * 8 + lr;
            pa[0] = Ps[w][lq][c];     pa[1] = Ps[w][lq + 8][c];
            pa[2] = Ps[w][lq][c + 4]; pa[3] = Ps[w][lq + 8][c + 4];
            #pragma unroll
            for (int n_ = 0; n_ < 8; n_++) {
                uint32_t vb[2];
                vb[0] = Vs[s * 8 + lr][n_ * 8 + lq];
                vb[1] = Vs[s * 8 + lr + 4][n_ * 8 + lq];
                mma_tf32(oacc[n_], pa, vb);
            }
        }
        __syncwarp();
    }

    // ---- epilogue ----
    float inv0 = 1.0f / l0, inv1 = 1.0f / l1;
    int b = bh >> 3, h = bh & 7;
    #pragma unroll
    for (int n_ = 0; n_ < 8; n_++) {
        int cgl = h * 64 + n_ * 8 + 2 * lr;
        float2 v0 = {oacc[n_][0] * inv0, oacc[n_][1] * inv0};
        float2 v1 = {oacc[n_][2] * inv1, oacc[n_][3] * inv1};
        *(float2*)&g_attn[((long)b * LL + r0g) * EQ + cgl] = v0;
        *(float2*)&g_attn[((long)b * LL + r0g + 8) * EQ + cgl] = v1;
    }
}

// =============================================================================
// G2: fused rollout + output projection. out[b,n,s,e] = attn[b,s,:] @ wbig[n]
// grid (64, 4, 8), 256 threads
// =============================================================================
__global__ __launch_bounds__(256) void out_gemm(const float* __restrict__ bo,
                                                float* __restrict__ out) {
    float acc[4][4][4] = {};
    int nz = blockIdx.z;
    int m0 = blockIdx.x * 128, n0 = blockIdx.y * 128;
    gemm128_tf32(g_attn + (long)m0 * 512, 512, g_wbig + (long)nz * EQ * EQ + n0, 512, acc);

    int tid = threadIdx.x;
    int wid = tid >> 5, lane = tid & 31;
    int wm = (wid & 1) * 64, wn = (wid >> 1) * 32;
    int lq = lane >> 2, lr = lane & 3;

    #pragma unroll
    for (int i = 0; i < 4; i++) {
        int mrow = m0 + wm + 16 * i + lq;
        int b = mrow >> 11, s = mrow & 2047;
        float* orow = out + (((long)(b * NF + nz) * LL + s) * EQ);
        #pragma unroll
        for (int j = 0; j < 4; j++) {
            int col = n0 + wn + 8 * j + 2 * lr;
            float b0 = bo[col], b1 = bo[col + 1];
            float2 v0 = {acc[i][j][0] + b0, acc[i][j][1] + b1};
            float2 v1 = {acc[i][j][2] + b0, acc[i][j][3] + b1};
            *(float2*)&orow[col] = v0;
            *(float2*)&orow[col + 8 * EQ] = v1;
        }
    }
}

// =============================================================================
extern "C" void kernel_launch(void* const* d_in, const int* in_sizes, int n_in,
                              void* d_out, int out_size) {
    const float* query = (const float*)d_in[0];
    // d_in[1] = key, d_in[2] = value -- unused by reference forward
    const float* Wqkv  = (const float*)d_in[3];
    const float* bqkv  = (const float*)d_in[4];
    const float* Wo    = (const float*)d_in[5];
    const float* bo    = (const float*)d_in[6];
    const float* Xi    = (const float*)d_in[7];
    float* out = (float*)d_out;

    prep_powers<<<HH, 256>>>(Xi);
    prep_wbig<<<NF * HH, 256>>>(Wo);
    qkv_gemm<<<dim3((NB * LL) / 128, (3 * EQ) / 128), 256>>>(query, Wqkv, bqkv);
    attn_kernel<<<dim3(LL / 64, BHCNT), 128>>>();
    out_gemm<<<dim3((NB * LL) / 128, EQ / 128, NF), 256>>>(bo, out);
}

// round 6
// speedup vs baseline: 2.6643x; 1.1345x over previous
#include <cuda_runtime.h>
#include <cuda_bf16.h>
#include <cstdint>

// Problem constants
#define NB 4
#define LL 2048
#define EQ 512
#define HH 8
#define HD 64
#define NF 8
#define BHCNT (NB*HH)

// ------------------- device scratch -------------------
__device__ float g_q[BHCNT * LL * HD];       // tf32-rounded, pre-scaled by 0.125
__device__ float g_k[BHCNT * LL * HD];       // tf32-rounded
__device__ float g_v[BHCNT * LL * HD];       // tf32-rounded
__device__ float g_attn[NB * LL * EQ];       // tf32-rounded attention output
__device__ float g_M[NF * HH * HD * HD];
__device__ float g_wbig[NF * EQ * EQ];       // tf32-rounded fused weights
__device__ float g_qr[NB * LL * EQ];         // tf32-rounded query
__device__ float g_wq[EQ * 3 * EQ];          // tf32-rounded Wqkv

// ------------------- helpers -------------------
__device__ __forceinline__ uint32_t f2tf(float x) {
    uint32_t r;
    asm("cvt.rna.tf32.f32 %0, %1;" : "=r"(r) : "f"(x));
    return r;
}
__device__ __forceinline__ float f2tff(float x) { return __uint_as_float(f2tf(x)); }

__device__ __forceinline__ void mma_tf32(float d[4], const uint32_t a[4], const uint32_t b[2]) {
    asm volatile(
        "mma.sync.aligned.m16n8k8.row.col.f32.tf32.tf32.f32 "
        "{%0,%1,%2,%3}, {%4,%5,%6,%7}, {%8,%9}, {%0,%1,%2,%3};\n"
        : "+f"(d[0]), "+f"(d[1]), "+f"(d[2]), "+f"(d[3])
        : "r"(a[0]), "r"(a[1]), "r"(a[2]), "r"(a[3]), "r"(b[0]), "r"(b[1]));
}

__device__ __forceinline__ uint32_t smem_u32(const void* p) {
    return (uint32_t)__cvta_generic_to_shared(p);
}
__device__ __forceinline__ void cp16(uint32_t s, const void* g) {
    asm volatile("cp.async.cg.shared.global [%0], [%1], 16;\n" :: "r"(s), "l"(g) : "memory");
}
#define CP_COMMIT() asm volatile("cp.async.commit_group;\n" ::: "memory")
#define CP_WAIT0()  asm volatile("cp.async.wait_group 0;\n" ::: "memory")

// =============================================================================
// Rounding passes (write device symbols directly)
// =============================================================================
__global__ void round_query(const float* __restrict__ in) {
    int i = blockIdx.x * blockDim.x + threadIdx.x;
    if (i < NB * LL * EQ / 4) {
        float4 v = ((const float4*)in)[i];
        v.x = f2tff(v.x); v.y = f2tff(v.y); v.z = f2tff(v.z); v.w = f2tff(v.w);
        ((float4*)g_qr)[i] = v;
    }
}
__global__ void round_wq(const float* __restrict__ in) {
    int i = blockIdx.x * blockDim.x + threadIdx.x;
    if (i < EQ * 3 * EQ / 4) {
        float4 v = ((const float4*)in)[i];
        v.x = f2tff(v.x); v.y = f2tff(v.y); v.z = f2tff(v.z); v.w = f2tff(v.w);
        ((float4*)g_wq)[i] = v;
    }
}

// =============================================================================
// P1: per-head T = I + (Xi - Xi^T); powers T^{n+1} -> g_M[n][h]
// =============================================================================
__global__ void prep_powers(const float* __restrict__ Xi) {
    int h = blockIdx.x;
    __shared__ float T[HD][HD];
    __shared__ float Ma[HD][HD];
    __shared__ float Mb[HD][HD];
    int t = threadIdx.x;

    for (int idx = t; idx < HD * HD; idx += 256) {
        int r = idx >> 6, c = idx & 63;
        float a = Xi[h * HD * HD + r * HD + c] - Xi[h * HD * HD + c * HD + r];
        float tv = a + ((r == c) ? 1.0f : 0.0f);
        T[r][c] = tv;
        Ma[r][c] = tv;
    }
    __syncthreads();

    for (int n = 0; n < NF; n++) {
        for (int idx = t; idx < HD * HD; idx += 256)
            g_M[(n * HH + h) * HD * HD + idx] = Ma[idx >> 6][idx & 63];
        if (n < NF - 1) {
            for (int idx = t; idx < HD * HD; idx += 256) {
                int r = idx >> 6, c = idx & 63;
                float sum = 0.0f;
                #pragma unroll 16
                for (int j = 0; j < HD; j++) sum += Ma[r][j] * T[j][c];
                Mb[r][c] = sum;
            }
            __syncthreads();
            for (int idx = t; idx < HD * HD; idx += 256)
                Ma[idx >> 6][idx & 63] = Mb[idx >> 6][idx & 63];
            __syncthreads();
        }
    }
}

// =============================================================================
// P2: g_wbig (tf32-rounded)
// =============================================================================
__global__ void prep_wbig(const float* __restrict__ Wo) {
    int nh = blockIdx.x;
    int n = nh >> 3, h = nh & 7;
    __shared__ float M[HD][HD];
    int t = threadIdx.x;
    for (int idx = t; idx < HD * HD; idx += 256)
        M[idx >> 6][idx & 63] = g_M[nh * HD * HD + idx];
    __syncthreads();

    for (int idx = t; idx < HD * EQ; idx += 256) {
        int r = idx >> 9, e = idx & 511;
        float sum = 0.0f;
        #pragma unroll 16
        for (int c = 0; c < HD; c++)
            sum += M[r][c] * Wo[(h * HD + c) * EQ + e];
        g_wbig[(n * EQ + h * HD + r) * EQ + e] = f2tff(sum);
    }
}

// =============================================================================
// Pipelined 128x128xK tf32 GEMM core. 2-stage cp.async, k-tile 16.
// Inputs MUST be tf32-pre-rounded. 256 threads = 8 warps (2m x 4n),
// warp tile 64x32. A pre-offset to m0 row, B pre-offset to n0 col.
// smem: As 20,480 B + Bs 17,408 B = 37,888 B
// Alignment: As row stride 80 B (16-div), Bs row stride 544 B (16-div).
// =============================================================================
template<int KTOT>
__device__ __forceinline__ void gemm128_pipe(
    const float* __restrict__ A, int lda,
    const float* __restrict__ B, int ldb,
    float acc[4][4][4])
{
    __shared__ __align__(16) uint32_t As[2][128][20];   // frag bank 20lq+lr: bijective
    __shared__ __align__(16) uint32_t Bs[2][16][136];   // frag bank 8lr+lq: bijective

    int tid = threadIdx.x;
    int wid = tid >> 5, lane = tid & 31;
    int wm = (wid & 1) * 64, wn = (wid >> 1) * 32;
    int lq = lane >> 2, lr = lane & 3;

    int ar = tid >> 1, ac = (tid & 1) * 8;
    int br = tid >> 4, bc = (tid & 15) * 8;

    const float* aptr = A + (long)ar * lda + ac;
    const float* bptr = B + (long)br * ldb + bc;
    uint32_t adst0 = smem_u32(&As[0][ar][ac]);
    uint32_t adst1 = smem_u32(&As[1][ar][ac]);
    uint32_t bdst0 = smem_u32(&Bs[0][br][bc]);
    uint32_t bdst1 = smem_u32(&Bs[1][br][bc]);

    // prologue: stage 0
    {
        #pragma unroll
        for (int u = 0; u < 2; u++) cp16(adst0 + 16 * u, aptr + 4 * u);
        #pragma unroll
        for (int u = 0; u < 2; u++) cp16(bdst0 + 16 * u, bptr + 4 * u);
        CP_COMMIT();
    }

    const int NT = KTOT / 16;
    for (int kt = 0; kt < NT; kt++) {
        CP_WAIT0();
        __syncthreads();
        if (kt + 1 < NT) {
            int k0 = (kt + 1) * 16;
            uint32_t ad = ((kt + 1) & 1) ? adst1 : adst0;
            uint32_t bd = ((kt + 1) & 1) ? bdst1 : bdst0;
            #pragma unroll
            for (int u = 0; u < 2; u++) cp16(ad + 16 * u, aptr + k0 + 4 * u);
            #pragma unroll
            for (int u = 0; u < 2; u++) cp16(bd + 16 * u, bptr + (long)k0 * ldb + 4 * u);
            CP_COMMIT();
        }
        int p = kt & 1;
        #pragma unroll
        for (int kk = 0; kk < 16; kk += 8) {
            uint32_t af[4][4], bf[4][2];
            #pragma unroll
            for (int i = 0; i < 4; i++) {
                int r = wm + 16 * i + lq;
                int c = kk + lr;
                af[i][0] = As[p][r][c];     af[i][1] = As[p][r + 8][c];
                af[i][2] = As[p][r][c + 4]; af[i][3] = As[p][r + 8][c + 4];
            }
            #pragma unroll
            for (int j = 0; j < 4; j++) {
                int n = wn + 8 * j + lq;
                int c = kk + lr;
                bf[j][0] = Bs[p][c][n]; bf[j][1] = Bs[p][c + 4][n];
            }
            #pragma unroll
            for (int i = 0; i < 4; i++)
                #pragma unroll
                for (int j = 0; j < 4; j++)
                    mma_tf32(acc[i][j], af[i], bf[j]);
        }
        __syncthreads();
    }
}

// =============================================================================
// G1: QKV projection (pre-rounded inputs) -> scatter tf32-rounded q/k/v.
// q pre-scaled by 0.125. grid (64, 12), 256 threads
// =============================================================================
__global__ __launch_bounds__(256) void qkv_gemm(const float* __restrict__ bias) {
    float acc[4][4][4] = {};
    int m0 = blockIdx.x * 128, n0 = blockIdx.y * 128;
    gemm128_pipe<512>(g_qr + (long)m0 * 512, 512, g_wq + n0, 1536, acc);

    int tid = threadIdx.x;
    int wid = tid >> 5, lane = tid & 31;
    int wm = (wid & 1) * 64, wn = (wid >> 1) * 32;
    int lq = lane >> 2, lr = lane & 3;

    #pragma unroll
    for (int i = 0; i < 4; i++) {
        int mrow = m0 + wm + 16 * i + lq;
        int b = mrow >> 11, s = mrow & 2047;
        #pragma unroll
        for (int j = 0; j < 4; j++) {
            int col = n0 + wn + 8 * j + 2 * lr;
            int which = col >> 9, rem = col & 511;
            int h = rem >> 6, d = rem & 63;
            float* dst = (which == 0) ? g_q : ((which == 1) ? g_k : g_v);
            float sc = (which == 0) ? 0.125f : 1.0f;
            float b0 = bias[col], b1 = bias[col + 1];
            float2 v0 = {f2tff((acc[i][j][0] + b0) * sc), f2tff((acc[i][j][1] + b1) * sc)};
            float2 v1 = {f2tff((acc[i][j][2] + b0) * sc), f2tff((acc[i][j][3] + b1) * sc)};
            long base = (((long)(b << 3) + h) * LL + s) * HD + d;
            *(float2*)&dst[base] = v0;
            *(float2*)&dst[base + 8 * HD] = v1;
        }
    }
}

// =============================================================================
// A: causal flash attention, tf32 MMA, cp.async 2-stage K/V pipeline.
// BM=64, BN=32, 4 warps. Q fragments loaded straight to registers.
// smem: Ks 17,408 + Vs 18,432 + Ps 9,216 = 45,056 B
// grid (32, 32), 128 threads
// =============================================================================
__global__ __launch_bounds__(128) void attn_kernel() {
    __shared__ __align__(16) uint32_t Ks[2][32][68];  // frag bank 4lq+lr: bijective
    __shared__ __align__(16) uint32_t Vs[2][32][72];  // frag bank 8lr+lq: bijective
    __shared__ __align__(16) uint32_t Ps[64][36];     // per-warp P scratch

    int bh = blockIdx.y;
    int qt = gridDim.x - 1 - blockIdx.x;   // heavy tiles first
    int q0 = qt * 64;
    int t = threadIdx.x;
    int w = t >> 5, lane = t & 31;
    int lq = lane >> 2, lr = lane & 3;

    // ---- issue K/V tile 0 prefetch ----
    {
        const float* kg = g_k + (long)bh * LL * HD;
        const float* vg = g_v + (long)bh * LL * HD;
        #pragma unroll
        for (int i = 0; i < 4; i++) {
            int idx = t + i * 128;
            int r = idx >> 4, c = (idx & 15) * 4;
            cp16(smem_u32(&Ks[0][r][c]), kg + (long)r * HD + c);
            cp16(smem_u32(&Vs[0][r][c]), vg + (long)r * HD + c);
        }
        CP_COMMIT();
    }

    // ---- Q fragments direct from gmem (overlaps with tile-0 cp.async) ----
    uint32_t qa[8][4];
    {
        const uint32_t* qg = (const uint32_t*)(g_q + ((long)bh * LL + q0) * HD);
        int rA = w * 16 + lq;
        #pragma unroll
        for (int s = 0; s < 8; s++) {
            int c = s * 8 + lr;
            qa[s][0] = qg[(long)rA * HD + c];
            qa[s][1] = qg[(long)(rA + 8) * HD + c];
            qa[s][2] = qg[(long)rA * HD + c + 4];
            qa[s][3] = qg[(long)(rA + 8) * HD + c + 4];
        }
    }

    float oacc[8][4];
    #pragma unroll
    for (int n_ = 0; n_ < 8; n_++)
        #pragma unroll
        for (int x = 0; x < 4; x++) oacc[n_][x] = 0.0f;
    float m0v = -1e30f, m1v = -1e30f, l0 = 0.0f, l1 = 0.0f;

    int r0g = q0 + w * 16 + lq;
    int wmaxrow = q0 + w * 16 + 15;
    int ntiles = 2 * qt + 2;

    for (int jt = 0; jt < ntiles; jt++) {
        int j0 = jt * 32;
        CP_WAIT0();
        __syncthreads();
        if (jt + 1 < ntiles) {
            int jn = (jt + 1) * 32;
            int buf = (jt + 1) & 1;
            const float* kg = g_k + ((long)bh * LL + jn) * HD;
            const float* vg = g_v + ((long)bh * LL + jn) * HD;
            #pragma unroll
            for (int i = 0; i < 4; i++) {
                int idx = t + i * 128;
                int r = idx >> 4, c = (idx & 15) * 4;
                cp16(smem_u32(&Ks[buf][r][c]), kg + (long)r * HD + c);
                cp16(smem_u32(&Vs[buf][r][c]), vg + (long)r * HD + c);
            }
            CP_COMMIT();
        }

        if (j0 <= wmaxrow) {
            int p = jt & 1;
            // ---- S = Q K^T ----
            float sacc[4][4] = {};
            #pragma unroll
            for (int s = 0; s < 8; s++) {
                uint32_t bf[4][2];
                #pragma unroll
                for (int j = 0; j < 4; j++) {
                    int n = j * 8 + lq, c = s * 8 + lr;
                    bf[j][0] = Ks[p][n][c]; bf[j][1] = Ks[p][n][c + 4];
                }
                #pragma unroll
                for (int j = 0; j < 4; j++) mma_tf32(sacc[j], qa[s], bf[j]);
            }

            // ---- causal mask ----
            if (j0 + 31 > q0) {
                #pragma unroll
                for (int j = 0; j < 4; j++) {
                    int kc = j0 + j * 8 + 2 * lr;
                    if (kc     > r0g)     sacc[j][0] = -1e30f;
                    if (kc + 1 > r0g)     sacc[j][1] = -1e30f;
                    if (kc     > r0g + 8) sacc[j][2] = -1e30f;
                    if (kc + 1 > r0g + 8) sacc[j][3] = -1e30f;
                }
            }

            // ---- online softmax ----
            float rm0 = -1e30f, rm1 = -1e30f;
            #pragma unroll
            for (int j = 0; j < 4; j++) {
                rm0 = fmaxf(rm0, fmaxf(sacc[j][0], sacc[j][1]));
                rm1 = fmaxf(rm1, fmaxf(sacc[j][2], sacc[j][3]));
            }
            rm0 = fmaxf(rm0, __shfl_xor_sync(0xffffffffu, rm0, 1));
            rm0 = fmaxf(rm0, __shfl_xor_sync(0xffffffffu, rm0, 2));
            rm1 = fmaxf(rm1, __shfl_xor_sync(0xffffffffu, rm1, 1));
            rm1 = fmaxf(rm1, __shfl_xor_sync(0xffffffffu, rm1, 2));
            float nm0 = fmaxf(m0v, rm0), nm1 = fmaxf(m1v, rm1);
            float c0 = __expf(m0v - nm0), c1 = __expf(m1v - nm1);
            m0v = nm0; m1v = nm1;

            float rs0 = 0.0f, rs1 = 0.0f;
            uint32_t pu[4][4];
            #pragma unroll
            for (int j = 0; j < 4; j++) {
                float p0 = __expf(sacc[j][0] - nm0);
                float p1 = __expf(sacc[j][1] - nm0);
                float p2 = __expf(sacc[j][2] - nm1);
                float p3 = __expf(sacc[j][3] - nm1);
                rs0 += p0 + p1; rs1 += p2 + p3;
                pu[j][0] = f2tf(p0); pu[j][1] = f2tf(p1);
                pu[j][2] = f2tf(p2); pu[j][3] = f2tf(p3);
            }
            rs0 += __shfl_xor_sync(0xffffffffu, rs0, 1);
            rs0 += __shfl_xor_sync(0xffffffffu, rs0, 2);
            rs1 += __shfl_xor_sync(0xffffffffu, rs1, 1);
            rs1 += __shfl_xor_sync(0xffffffffu, rs1, 2);
            l0 = l0 * c0 + rs0;
            l1 = l1 * c1 + rs1;
            #pragma unroll
            for (int n_ = 0; n_ < 8; n_++) {
                oacc[n_][0] *= c0; oacc[n_][1] *= c0;
                oacc[n_][2] *= c1; oacc[n_][3] *= c1;
            }

            // ---- P -> per-warp smem rows, reload as A-frags ----
            __syncwarp();
            #pragma unroll
            for (int j = 0; j < 4; j++) {
                *(uint2*)&Ps[w * 16 + lq][j * 8 + 2 * lr]     = make_uint2(pu[j][0], pu[j][1]);
                *(uint2*)&Ps[w * 16 + lq + 8][j * 8 + 2 * lr] = make_uint2(pu[j][2], pu[j][3]);
            }
            __syncwarp();

            // ---- O += P V ----
            #pragma unroll
            for (int s = 0; s < 4; s++) {
                uint32_t pa[4];
                int c = s * 8 + lr;
                pa[0] = Ps[w * 16 + lq][c];     pa[1] = Ps[w * 16 + lq + 8][c];
                pa[2] = Ps[w * 16 + lq][c + 4]; pa[3] = Ps[w * 16 + lq + 8][c + 4];
                #pragma unroll
                for (int n_ = 0; n_ < 8; n_++) {
                    uint32_t vb[2];
                    vb[0] = Vs[p][s * 8 + lr][n_ * 8 + lq];
                    vb[1] = Vs[p][s * 8 + lr + 4][n_ * 8 + lq];
                    mma_tf32(oacc[n_], pa, vb);
                }
            }
            __syncwarp();
        }
        __syncthreads();
    }

    // ---- epilogue: rounded tf32 output ----
    float inv0 = 1.0f / l0, inv1 = 1.0f / l1;
    int b = bh >> 3, h = bh & 7;
    #pragma unroll
    for (int n_ = 0; n_ < 8; n_++) {
        int cgl = h * 64 + n_ * 8 + 2 * lr;
        float2 v0 = {f2tff(oacc[n_][0] * inv0), f2tff(oacc[n_][1] * inv0)};
        float2 v1 = {f2tff(oacc[n_][2] * inv1), f2tff(oacc[n_][3] * inv1)};
        *(float2*)&g_attn[((long)b * LL + r0g) * EQ + cgl] = v0;
        *(float2*)&g_attn[((long)b * LL + r0g + 8) * EQ + cgl] = v1;
    }
}

// =============================================================================
// G2: fused rollout + output projection. grid (64, 4, 8), 256 threads
// =============================================================================
__global__ __launch_bounds__(256) void out_gemm(const float* __restrict__ bo,
                                                float* __restrict__ out) {
    float acc[4][4][4] = {};
    int nz = blockIdx.z;
    int m0 = blockIdx.x * 128, n0 = blockIdx.y * 128;
    gemm128_pipe<512>(g_attn + (long)m0 * 512, 512, g_wbig + (long)nz * EQ * EQ + n0, 512, acc);

    int tid = threadIdx.x;
    int wid = tid >> 5, lane = tid & 31;
    int wm = (wid & 1) * 64, wn = (wid >> 1) * 32;
    int lq = lane >> 2, lr = lane & 3;

    #pragma unroll
    for (int i = 0; i < 4; i++) {
        int mrow = m0 + wm + 16 * i + lq;
        int b = mrow >> 11, s = mrow & 2047;
        float* orow = out + (((long)(b * NF + nz) * LL + s) * EQ);
        #pragma unroll
        for (int j = 0; j < 4; j++) {
            int col = n0 + wn + 8 * j + 2 * lr;
            float b0 = bo[col], b1 = bo[col + 1];
            float2 v0 = {acc[i][j][0] + b0, acc[i][j][1] + b1};
            float2 v1 = {acc[i][j][2] + b0, acc[i][j][3] + b1};
            *(float2*)&orow[col] = v0;
            *(float2*)&orow[col + 8 * EQ] = v1;
        }
    }
}

// =============================================================================
extern "C" void kernel_launch(void* const* d_in, const int* in_sizes, int n_in,
                              void* d_out, int out_size) {
    const float* query = (const float*)d_in[0];
    const float* Wqkv  = (const float*)d_in[3];
    const float* bqkv  = (const float*)d_in[4];
    const float* Wo    = (const float*)d_in[5];
    const float* bo    = (const float*)d_in[6];
    const float* Xi    = (const float*)d_in[7];
    float* out = (float*)d_out;

    round_query<<<(NB * LL * EQ / 4 + 255) / 256, 256>>>(query);
    round_wq<<<(EQ * 3 * EQ / 4 + 255) / 256, 256>>>(Wqkv);
    prep_powers<<<HH, 256>>>(Xi);
    prep_wbig<<<NF * HH, 256>>>(Wo);
    qkv_gemm<<<dim3((NB * LL) / 128, (3 * EQ) / 128), 256>>>(bqkv);
    attn_kernel<<<dim3(LL / 64, BHCNT), 128>>>();
    out_gemm<<<dim3((NB * LL) / 128, EQ / 128, NF), 256>>>(bo, out);
}

// round 7
// speedup vs baseline: 3.4169x; 1.2825x over previous
#include <cuda_runtime.h>
#include <cuda_bf16.h>
#include <cstdint>

// Problem constants
#define NB 4
#define LL 2048
#define EQ 512
#define HH 8
#define HD 64
#define NF 8
#define BHCNT (NB*HH)

// ------------------- device scratch -------------------
__device__ float g_q[BHCNT * LL * HD];       // tf32-rounded, pre-scaled by 0.125
__device__ float g_k[BHCNT * LL * HD];       // tf32-rounded
__device__ float g_v[BHCNT * LL * HD];       // tf32-rounded
__device__ float g_attn[NB * LL * EQ];       // tf32-rounded attention output
__device__ float g_M[NF * HH * HD * HD];
__device__ float g_wbig[NF * EQ * EQ];       // tf32-rounded fused weights
__device__ float g_qr[NB * LL * EQ];         // tf32-rounded query
__device__ float g_wq[EQ * 3 * EQ];          // tf32-rounded Wqkv

// ------------------- helpers -------------------
__device__ __forceinline__ uint32_t f2tf(float x) {
    uint32_t r;
    asm("cvt.rna.tf32.f32 %0, %1;" : "=r"(r) : "f"(x));
    return r;
}
__device__ __forceinline__ float f2tff(float x) { return __uint_as_float(f2tf(x)); }

__device__ __forceinline__ void mma_tf32(float d[4], const uint32_t a[4], const uint32_t b[2]) {
    asm volatile(
        "mma.sync.aligned.m16n8k8.row.col.f32.tf32.tf32.f32 "
        "{%0,%1,%2,%3}, {%4,%5,%6,%7}, {%8,%9}, {%0,%1,%2,%3};\n"
        : "+f"(d[0]), "+f"(d[1]), "+f"(d[2]), "+f"(d[3])
        : "r"(a[0]), "r"(a[1]), "r"(a[2]), "r"(a[3]), "r"(b[0]), "r"(b[1]));
}

__device__ __forceinline__ uint32_t smem_u32(const void* p) {
    return (uint32_t)__cvta_generic_to_shared(p);
}
__device__ __forceinline__ void cp16(uint32_t s, const void* g) {
    asm volatile("cp.async.cg.shared.global [%0], [%1], 16;\n" :: "r"(s), "l"(g) : "memory");
}
#define CP_COMMIT() asm volatile("cp.async.commit_group;\n" ::: "memory")
#define CP_WAIT0()  asm volatile("cp.async.wait_group 0;\n" ::: "memory")

// =============================================================================
// Rounding passes (write device symbols directly)
// =============================================================================
__global__ void round_query(const float* __restrict__ in) {
    int i = blockIdx.x * blockDim.x + threadIdx.x;
    if (i < NB * LL * EQ / 4) {
        float4 v = ((const float4*)in)[i];
        v.x = f2tff(v.x); v.y = f2tff(v.y); v.z = f2tff(v.z); v.w = f2tff(v.w);
        ((float4*)g_qr)[i] = v;
    }
}
__global__ void round_wq(const float* __restrict__ in) {
    int i = blockIdx.x * blockDim.x + threadIdx.x;
    if (i < EQ * 3 * EQ / 4) {
        float4 v = ((const float4*)in)[i];
        v.x = f2tff(v.x); v.y = f2tff(v.y); v.z = f2tff(v.z); v.w = f2tff(v.w);
        ((float4*)g_wq)[i] = v;
    }
}

// =============================================================================
// P1: per-head T = I + (Xi - Xi^T); powers T^{n+1} -> g_M[n][h]
// =============================================================================
__global__ void prep_powers(const float* __restrict__ Xi) {
    int h = blockIdx.x;
    __shared__ float T[HD][HD];
    __shared__ float Ma[HD][HD];
    __shared__ float Mb[HD][HD];
    int t = threadIdx.x;

    for (int idx = t; idx < HD * HD; idx += 256) {
        int r = idx >> 6, c = idx & 63;
        float a = Xi[h * HD * HD + r * HD + c] - Xi[h * HD * HD + c * HD + r];
        float tv = a + ((r == c) ? 1.0f : 0.0f);
        T[r][c] = tv;
        Ma[r][c] = tv;
    }
    __syncthreads();

    for (int n = 0; n < NF; n++) {
        for (int idx = t; idx < HD * HD; idx += 256)
            g_M[(n * HH + h) * HD * HD + idx] = Ma[idx >> 6][idx & 63];
        if (n < NF - 1) {
            for (int idx = t; idx < HD * HD; idx += 256) {
                int r = idx >> 6, c = idx & 63;
                float sum = 0.0f;
                #pragma unroll 16
                for (int j = 0; j < HD; j++) sum += Ma[r][j] * T[j][c];
                Mb[r][c] = sum;
            }
            __syncthreads();
            for (int idx = t; idx < HD * HD; idx += 256)
                Ma[idx >> 6][idx & 63] = Mb[idx >> 6][idx & 63];
            __syncthreads();
        }
    }
}

// =============================================================================
// P2: g_wbig[n][h*64+r][e] = sum_c M[r][c] * Wo[h*64+c][e]  (tf32-rounded)
// Tiled: grid (64 nh, 4 e-chunks), 256 threads. M + Wo tile staged in smem
// (16 KB + 32 KB = 48 KB exactly). Each thread: 8 r x 4 e outputs.
// =============================================================================
__global__ __launch_bounds__(256) void prep_wbig(const float* __restrict__ Wo) {
    __shared__ float M[HD][HD];        // 16 KB
    __shared__ float Ws[HD][128];      // 32 KB
    int nh = blockIdx.x;
    int e0 = blockIdx.y * 128;
    int n = nh >> 3, h = nh & 7;
    int t = threadIdx.x;

    // stage M (4096 floats, 4 float4/thread)
    {
        const float4* src = (const float4*)(g_M + nh * HD * HD);
        float4* dst = (float4*)M;
        #pragma unroll
        for (int i = 0; i < 4; i++) dst[t + i * 256] = src[t + i * 256];
    }
    // stage Wo tile rows h*64..h*64+63, cols e0..e0+127 (8 float4/thread)
    {
        #pragma unroll
        for (int i = 0; i < 8; i++) {
            int lin = t + i * 256;            // float4 index, 0..2047
            int row = lin >> 5, c4 = lin & 31;
            *(float4*)&Ws[row][c4 * 4] =
                *(const float4*)&Wo[(h * HD + row) * EQ + e0 + c4 * 4];
        }
    }
    __syncthreads();

    int ecol = t & 31;          // float4 column within 128-chunk
    int r8 = t >> 5;            // row group 0..7
    float4 acc[8];
    #pragma unroll
    for (int i = 0; i < 8; i++) acc[i] = make_float4(0.f, 0.f, 0.f, 0.f);

    #pragma unroll 8
    for (int c = 0; c < HD; c++) {
        float4 wv = *(const float4*)&Ws[c][ecol * 4];
        #pragma unroll
        for (int i = 0; i < 8; i++) {
            float mv = M[r8 * 8 + i][c];     // warp broadcast
            acc[i].x += mv * wv.x; acc[i].y += mv * wv.y;
            acc[i].z += mv * wv.z; acc[i].w += mv * wv.w;
        }
    }

    #pragma unroll
    for (int i = 0; i < 8; i++) {
        int r = r8 * 8 + i;
        float4 v = {f2tff(acc[i].x), f2tff(acc[i].y), f2tff(acc[i].z), f2tff(acc[i].w)};
        *(float4*)&g_wbig[(n * EQ + h * HD + r) * EQ + e0 + ecol * 4] = v;
    }
}

// =============================================================================
// Pipelined 128x128xK tf32 GEMM core. 2-stage cp.async, k-tile 16,
// ONE barrier per tile (top wait+sync also guards buffer reuse).
// smem: As 20,480 B + Bs 17,408 B = 37,888 B
// =============================================================================
template<int KTOT>
__device__ __forceinline__ void gemm128_pipe(
    const float* __restrict__ A, int lda,
    const float* __restrict__ B, int ldb,
    float acc[4][4][4])
{
    __shared__ __align__(16) uint32_t As[2][128][20];   // frag bank 20lq+lr: bijective
    __shared__ __align__(16) uint32_t Bs[2][16][136];   // frag bank 8lr+lq: bijective

    int tid = threadIdx.x;
    int wid = tid >> 5, lane = tid & 31;
    int wm = (wid & 1) * 64, wn = (wid >> 1) * 32;
    int lq = lane >> 2, lr = lane & 3;

    int ar = tid >> 1, ac = (tid & 1) * 8;
    int br = tid >> 4, bc = (tid & 15) * 8;

    const float* aptr = A + (long)ar * lda + ac;
    const float* bptr = B + (long)br * ldb + bc;
    uint32_t adst0 = smem_u32(&As[0][ar][ac]);
    uint32_t adst1 = smem_u32(&As[1][ar][ac]);
    uint32_t bdst0 = smem_u32(&Bs[0][br][bc]);
    uint32_t bdst1 = smem_u32(&Bs[1][br][bc]);

    // prologue: stage 0
    {
        #pragma unroll
        for (int u = 0; u < 2; u++) cp16(adst0 + 16 * u, aptr + 4 * u);
        #pragma unroll
        for (int u = 0; u < 2; u++) cp16(bdst0 + 16 * u, bptr + 4 * u);
        CP_COMMIT();
    }

    const int NT = KTOT / 16;
    for (int kt = 0; kt < NT; kt++) {
        CP_WAIT0();
        __syncthreads();   // data visible AND all threads done with other buffer
        if (kt + 1 < NT) {
            int k0 = (kt + 1) * 16;
            uint32_t ad = ((kt + 1) & 1) ? adst1 : adst0;
            uint32_t bd = ((kt + 1) & 1) ? bdst1 : bdst0;
            #pragma unroll
            for (int u = 0; u < 2; u++) cp16(ad + 16 * u, aptr + k0 + 4 * u);
            #pragma unroll
            for (int u = 0; u < 2; u++) cp16(bd + 16 * u, bptr + (long)k0 * ldb + 4 * u);
            CP_COMMIT();
        }
        int p = kt & 1;
        #pragma unroll
        for (int kk = 0; kk < 16; kk += 8) {
            uint32_t af[4][4], bf[4][2];
            #pragma unroll
            for (int i = 0; i < 4; i++) {
                int r = wm + 16 * i + lq;
                int c = kk + lr;
                af[i][0] = As[p][r][c];     af[i][1] = As[p][r + 8][c];
                af[i][2] = As[p][r][c + 4]; af[i][3] = As[p][r + 8][c + 4];
            }
            #pragma unroll
            for (int j = 0; j < 4; j++) {
                int n = wn + 8 * j + lq;
                int c = kk + lr;
                bf[j][0] = Bs[p][c][n]; bf[j][1] = Bs[p][c + 4][n];
            }
            #pragma unroll
            for (int i = 0; i < 4; i++)
                #pragma unroll
                for (int j = 0; j < 4; j++)
                    mma_tf32(acc[i][j], af[i], bf[j]);
        }
    }
}

// =============================================================================
// G1: QKV projection -> scatter tf32-rounded q/k/v (q pre-scaled by 0.125).
// grid (64, 12), 256 threads
// =============================================================================
__global__ __launch_bounds__(256) void qkv_gemm(const float* __restrict__ bias) {
    float acc[4][4][4] = {};
    int m0 = blockIdx.x * 128, n0 = blockIdx.y * 128;
    gemm128_pipe<512>(g_qr + (long)m0 * 512, 512, g_wq + n0, 1536, acc);

    int tid = threadIdx.x;
    int wid = tid >> 5, lane = tid & 31;
    int wm = (wid & 1) * 64, wn = (wid >> 1) * 32;
    int lq = lane >> 2, lr = lane & 3;

    #pragma unroll
    for (int i = 0; i < 4; i++) {
        int mrow = m0 + wm + 16 * i + lq;
        int b = mrow >> 11, s = mrow & 2047;
        #pragma unroll
        for (int j = 0; j < 4; j++) {
            int col = n0 + wn + 8 * j + 2 * lr;
            int which = col >> 9, rem = col & 511;
            int h = rem >> 6, d = rem & 63;
            float* dst = (which == 0) ? g_q : ((which == 1) ? g_k : g_v);
            float sc = (which == 0) ? 0.125f : 1.0f;
            float b0 = bias[col], b1 = bias[col + 1];
            float2 v0 = {f2tff((acc[i][j][0] + b0) * sc), f2tff((acc[i][j][1] + b1) * sc)};
            float2 v1 = {f2tff((acc[i][j][2] + b0) * sc), f2tff((acc[i][j][3] + b1) * sc)};
            long base = (((long)(b << 3) + h) * LL + s) * HD + d;
            *(float2*)&dst[base] = v0;
            *(float2*)&dst[base + 8 * HD] = v1;
        }
    }
}

// =============================================================================
// A: causal flash attention, tf32 MMA, cp.async 2-stage K/V pipeline.
// BM=64, BN=32, 4 warps, one barrier per tile. Q fragments in registers.
// smem: 45,056 B. grid (32, 32), 128 threads
// =============================================================================
__global__ __launch_bounds__(128) void attn_kernel() {
    __shared__ __align__(16) uint32_t Ks[2][32][68];
    __shared__ __align__(16) uint32_t Vs[2][32][72];
    __shared__ __align__(16) uint32_t Ps[64][36];

    int bh = blockIdx.y;
    int qt = gridDim.x - 1 - blockIdx.x;   // heavy tiles first
    int q0 = qt * 64;
    int t = threadIdx.x;
    int w = t >> 5, lane = t & 31;
    int lq = lane >> 2, lr = lane & 3;

    // ---- issue K/V tile 0 prefetch ----
    {
        const float* kg = g_k + (long)bh * LL * HD;
        const float* vg = g_v + (long)bh * LL * HD;
        #pragma unroll
        for (int i = 0; i < 4; i++) {
            int idx = t + i * 128;
            int r = idx >> 4, c = (idx & 15) * 4;
            cp16(smem_u32(&Ks[0][r][c]), kg + (long)r * HD + c);
            cp16(smem_u32(&Vs[0][r][c]), vg + (long)r * HD + c);
        }
        CP_COMMIT();
    }

    // ---- Q fragments direct from gmem ----
    uint32_t qa[8][4];
    {
        const uint32_t* qg = (const uint32_t*)(g_q + ((long)bh * LL + q0) * HD);
        int rA = w * 16 + lq;
        #pragma unroll
        for (int s = 0; s < 8; s++) {
            int c = s * 8 + lr;
            qa[s][0] = qg[(long)rA * HD + c];
            qa[s][1] = qg[(long)(rA + 8) * HD + c];
            qa[s][2] = qg[(long)rA * HD + c + 4];
            qa[s][3] = qg[(long)(rA + 8) * HD + c + 4];
        }
    }

    float oacc[8][4];
    #pragma unroll
    for (int n_ = 0; n_ < 8; n_++)
        #pragma unroll
        for (int x = 0; x < 4; x++) oacc[n_][x] = 0.0f;
    float m0v = -1e30f, m1v = -1e30f, l0 = 0.0f, l1 = 0.0f;

    int r0g = q0 + w * 16 + lq;
    int wmaxrow = q0 + w * 16 + 15;
    int ntiles = 2 * qt + 2;

    for (int jt = 0; jt < ntiles; jt++) {
        int j0 = jt * 32;
        CP_WAIT0();
        __syncthreads();   // data visible AND all warps done with other buffer
        if (jt + 1 < ntiles) {
            int jn = (jt + 1) * 32;
            int buf = (jt + 1) & 1;
            const float* kg = g_k + ((long)bh * LL + jn) * HD;
            const float* vg = g_v + ((long)bh * LL + jn) * HD;
            #pragma unroll
            for (int i = 0; i < 4; i++) {
                int idx = t + i * 128;
                int r = idx >> 4, c = (idx & 15) * 4;
                cp16(smem_u32(&Ks[buf][r][c]), kg + (long)r * HD + c);
                cp16(smem_u32(&Vs[buf][r][c]), vg + (long)r * HD + c);
            }
            CP_COMMIT();
        }

        if (j0 <= wmaxrow) {
            int p = jt & 1;
            // ---- S = Q K^T ----
            float sacc[4][4] = {};
            #pragma unroll
            for (int s = 0; s < 8; s++) {
                uint32_t bf[4][2];
                #pragma unroll
                for (int j = 0; j < 4; j++) {
                    int n = j * 8 + lq, c = s * 8 + lr;
                    bf[j][0] = Ks[p][n][c]; bf[j][1] = Ks[p][n][c + 4];
                }
                #pragma unroll
                for (int j = 0; j < 4; j++) mma_tf32(sacc[j], qa[s], bf[j]);
            }

            // ---- causal mask ----
            if (j0 + 31 > q0) {
                #pragma unroll
                for (int j = 0; j < 4; j++) {
                    int kc = j0 + j * 8 + 2 * lr;
                    if (kc     > r0g)     sacc[j][0] = -1e30f;
                    if (kc + 1 > r0g)     sacc[j][1] = -1e30f;
                    if (kc     > r0g + 8) sacc[j][2] = -1e30f;
                    if (kc + 1 > r0g + 8) sacc[j][3] = -1e30f;
                }
            }

            // ---- online softmax ----
            float rm0 = -1e30f, rm1 = -1e30f;
            #pragma unroll
            for (int j = 0; j < 4; j++) {
                rm0 = fmaxf(rm0, fmaxf(sacc[j][0], sacc[j][1]));
                rm1 = fmaxf(rm1, fmaxf(sacc[j][2], sacc[j][3]));
            }
            rm0 = fmaxf(rm0, __shfl_xor_sync(0xffffffffu, rm0, 1));
            rm0 = fmaxf(rm0, __shfl_xor_sync(0xffffffffu, rm0, 2));
            rm1 = fmaxf(rm1, __shfl_xor_sync(0xffffffffu, rm1, 1));
            rm1 = fmaxf(rm1, __shfl_xor_sync(0xffffffffu, rm1, 2));
            float nm0 = fmaxf(m0v, rm0), nm1 = fmaxf(m1v, rm1);
            float c0 = __expf(m0v - nm0), c1 = __expf(m1v - nm1);
            m0v = nm0; m1v = nm1;

            float rs0 = 0.0f, rs1 = 0.0f;
            uint32_t pu[4][4];
            #pragma unroll
            for (int j = 0; j < 4; j++) {
                float p0 = __expf(sacc[j][0] - nm0);
                float p1 = __expf(sacc[j][1] - nm0);
                float p2 = __expf(sacc[j][2] - nm1);
                float p3 = __expf(sacc[j][3] - nm1);
                rs0 += p0 + p1; rs1 += p2 + p3;
                pu[j][0] = f2tf(p0); pu[j][1] = f2tf(p1);
                pu[j][2] = f2tf(p2); pu[j][3] = f2tf(p3);
            }
            rs0 += __shfl_xor_sync(0xffffffffu, rs0, 1);
            rs0 += __shfl_xor_sync(0xffffffffu, rs0, 2);
            rs1 += __shfl_xor_sync(0xffffffffu, rs1, 1);
            rs1 += __shfl_xor_sync(0xffffffffu, rs1, 2);
            l0 = l0 * c0 + rs0;
            l1 = l1 * c1 + rs1;
            #pragma unroll
            for (int n_ = 0; n_ < 8; n_++) {
                oacc[n_][0] *= c0; oacc[n_][1] *= c0;
                oacc[n_][2] *= c1; oacc[n_][3] *= c1;
            }

            // ---- P -> per-warp smem rows, reload as A-frags ----
            __syncwarp();
            #pragma unroll
            for (int j = 0; j < 4; j++) {
                *(uint2*)&Ps[w * 16 + lq][j * 8 + 2 * lr]     = make_uint2(pu[j][0], pu[j][1]);
                *(uint2*)&Ps[w * 16 + lq + 8][j * 8 + 2 * lr] = make_uint2(pu[j][2], pu[j][3]);
            }
            __syncwarp();

            // ---- O += P V ----
            #pragma unroll
            for (int s = 0; s < 4; s++) {
                uint32_t pa[4];
                int c = s * 8 + lr;
                pa[0] = Ps[w * 16 + lq][c];     pa[1] = Ps[w * 16 + lq + 8][c];
                pa[2] = Ps[w * 16 + lq][c + 4]; pa[3] = Ps[w * 16 + lq + 8][c + 4];
                #pragma unroll
                for (int n_ = 0; n_ < 8; n_++) {
                    uint32_t vb[2];
                    vb[0] = Vs[p][s * 8 + lr][n_ * 8 + lq];
                    vb[1] = Vs[p][s * 8 + lr + 4][n_ * 8 + lq];
                    mma_tf32(oacc[n_], pa, vb);
                }
            }
            __syncwarp();
        }
    }

    // ---- epilogue: rounded tf32 output ----
    float inv0 = 1.0f / l0, inv1 = 1.0f / l1;
    int b = bh >> 3, h = bh & 7;
    #pragma unroll
    for (int n_ = 0; n_ < 8; n_++) {
        int cgl = h * 64 + n_ * 8 + 2 * lr;
        float2 v0 = {f2tff(oacc[n_][0] * inv0), f2tff(oacc[n_][1] * inv0)};
        float2 v1 = {f2tff(oacc[n_][2] * inv1), f2tff(oacc[n_][3] * inv1)};
        *(float2*)&g_attn[((long)b * LL + r0g) * EQ + cgl] = v0;
        *(float2*)&g_attn[((long)b * LL + r0g + 8) * EQ + cgl] = v1;
    }
}

// =============================================================================
// G2: fused rollout + output projection. grid (64, 4, 8), 256 threads
// =============================================================================
__global__ __launch_bounds__(256) void out_gemm(const float* __restrict__ bo,
                                                float* __restrict__ out) {
    float acc[4][4][4] = {};
    int nz = blockIdx.z;
    int m0 = blockIdx.x * 128, n0 = blockIdx.y * 128;
    gemm128_pipe<512>(g_attn + (long)m0 * 512, 512, g_wbig + (long)nz * EQ * EQ + n0, 512, acc);

    int tid = threadIdx.x;
    int wid = tid >> 5, lane = tid & 31;
    int wm = (wid & 1) * 64, wn = (wid >> 1) * 32;
    int lq = lane >> 2, lr = lane & 3;

    #pragma unroll
    for (int i = 0; i < 4; i++) {
        int mrow = m0 + wm + 16 * i + lq;
        int b = mrow >> 11, s = mrow & 2047;
        float* orow = out + (((long)(b * NF + nz) * LL + s) * EQ);
        #pragma unroll
        for (int j = 0; j < 4; j++) {
            int col = n0 + wn + 8 * j + 2 * lr;
            float b0 = bo[col], b1 = bo[col + 1];
            float2 v0 = {acc[i][j][0] + b0, acc[i][j][1] + b1};
            float2 v1 = {acc[i][j][2] + b0, acc[i][j][3] + b1};
            *(float2*)&orow[col] = v0;
            *(float2*)&orow[col + 8 * EQ] = v1;
        }
    }
}

// =============================================================================
extern "C" void kernel_launch(void* const* d_in, const int* in_sizes, int n_in,
                              void* d_out, int out_size) {
    const float* query = (const float*)d_in[0];
    const float* Wqkv  = (const float*)d_in[3];
    const float* bqkv  = (const float*)d_in[4];
    const float* Wo    = (const float*)d_in[5];
    const float* bo    = (const float*)d_in[6];
    const float* Xi    = (const float*)d_in[7];
    float* out = (float*)d_out;

    round_query<<<(NB * LL * EQ / 4 + 255) / 256, 256>>>(query);
    round_wq<<<(EQ * 3 * EQ / 4 + 255) / 256, 256>>>(Wqkv);
    prep_powers<<<HH, 256>>>(Xi);
    prep_wbig<<<dim3(NF * HH, EQ / 128), 256>>>(Wo);
    qkv_gemm<<<dim3((NB * LL) / 128, (3 * EQ) / 128), 256>>>(bqkv);
    attn_kernel<<<dim3(LL / 64, BHCNT), 128>>>();
    out_gemm<<<dim3((NB * LL) / 128, EQ / 128, NF), 256>>>(bo, out);
}